// round 6
// baseline (speedup 1.0000x reference)
#include <cuda_runtime.h>
#include <math.h>

// Problem constants (from reference: B=4, T=4096, D=1024, H=4*D, 4 experts)
#define T_TOT 16384
#define DDIM  1024
#define HDIM  4096
#define NEXP  4

#define BM 64
#define BN 64
#define BK 16

// Scratch (allocation-free rule: __device__ globals)
__device__ int   g_counts[NEXP];
__device__ int   g_perm[NEXP * T_TOT];
__device__ float g_h[(size_t)T_TOT * HDIM];   // 256 MB hidden activations

// ---------------------------------------------------------------------------
// Expert grouping
// ---------------------------------------------------------------------------
__global__ void k_init_counts() {
    if (threadIdx.x < NEXP) g_counts[threadIdx.x] = 0;
}

__global__ void k_scatter(const int* __restrict__ mask) {
    int t = blockIdx.x * blockDim.x + threadIdx.x;
    if (t < T_TOT) {
        int e = mask[t];
        int pos = atomicAdd(&g_counts[e], 1);
        g_perm[e * T_TOT + pos] = t;
    }
}

// ---------------------------------------------------------------------------
// GEMM1: h[tok, j] = gelu( sum_{k<d_in} x[tok,k] * W1[j,k] + b1[j] ), j < d_hid
// Grouped by expert; rows gathered via g_perm.
// ---------------------------------------------------------------------------
__device__ __forceinline__ float gelu_exact(float v) {
    return 0.5f * v * (1.0f + erff(v * 0.70710678118654752f));
}

__global__ __launch_bounds__(256) void k_gemm1(const float* __restrict__ x,
                                               const float* __restrict__ W1,
                                               const float* __restrict__ b1) {
    const int m = blockIdx.z;
    const int count = g_counts[m];
    const int row0 = blockIdx.y * BM;
    if (row0 >= count) return;
    const int dhid = HDIM >> (NEXP - 1 - m);
    const int col0 = blockIdx.x * BN;
    if (col0 >= dhid) return;
    const int din = DDIM >> (NEXP - 1 - m);

    __shared__ __align__(16) float As[BK][BM + 4];
    __shared__ __align__(16) float Bs[BK][BN + 4];

    const int tid  = threadIdx.x;
    const int lrow = tid >> 2;          // 0..63  (tile row this thread loads)
    const int lk4  = (tid & 3) * 4;     // 0,4,8,12

    const int arow = row0 + lrow;
    const bool avalid = (arow < count);
    const int tok_ld = avalid ? g_perm[m * T_TOT + arow] : 0;
    const float* aptr = x + (size_t)tok_ld * DDIM;
    const float* bptr = W1 + (size_t)(col0 + lrow) * DDIM;   // brow < dhid (64-aligned)

    const int tx = tid & 15, ty = tid >> 4;
    float acc[4][4] = {};

    for (int k0 = 0; k0 < din; k0 += BK) {
        float4 av = avalid ? *(const float4*)(aptr + k0 + lk4)
                           : make_float4(0.f, 0.f, 0.f, 0.f);
        float4 bv = *(const float4*)(bptr + k0 + lk4);
        As[lk4 + 0][lrow] = av.x; As[lk4 + 1][lrow] = av.y;
        As[lk4 + 2][lrow] = av.z; As[lk4 + 3][lrow] = av.w;
        Bs[lk4 + 0][lrow] = bv.x; Bs[lk4 + 1][lrow] = bv.y;
        Bs[lk4 + 2][lrow] = bv.z; Bs[lk4 + 3][lrow] = bv.w;
        __syncthreads();
#pragma unroll
        for (int k = 0; k < BK; k++) {
            float4 a = *(const float4*)&As[k][ty * 4];
            float4 b = *(const float4*)&Bs[k][tx * 4];
            acc[0][0] += a.x * b.x; acc[0][1] += a.x * b.y; acc[0][2] += a.x * b.z; acc[0][3] += a.x * b.w;
            acc[1][0] += a.y * b.x; acc[1][1] += a.y * b.y; acc[1][2] += a.y * b.z; acc[1][3] += a.y * b.w;
            acc[2][0] += a.z * b.x; acc[2][1] += a.z * b.y; acc[2][2] += a.z * b.z; acc[2][3] += a.z * b.w;
            acc[3][0] += a.w * b.x; acc[3][1] += a.w * b.y; acc[3][2] += a.w * b.z; acc[3][3] += a.w * b.w;
        }
        __syncthreads();
    }

#pragma unroll
    for (int r = 0; r < 4; r++) {
        int grow = row0 + ty * 4 + r;
        if (grow < count) {
            int tok = g_perm[m * T_TOT + grow];
            float* hrow = g_h + (size_t)tok * HDIM;
#pragma unroll
            for (int c = 0; c < 4; c++) {
                int j = col0 + tx * 4 + c;
                hrow[j] = gelu_exact(acc[r][c] + b1[j]);
            }
        }
    }
}

// ---------------------------------------------------------------------------
// GEMM2: out[tok, d] = sum_{k<d_hid} h[tok,k] * W2[d,k] + b2[d]
// ---------------------------------------------------------------------------
__global__ __launch_bounds__(256) void k_gemm2(const float* __restrict__ W2,
                                               const float* __restrict__ b2,
                                               float* __restrict__ out) {
    const int m = blockIdx.z;
    const int count = g_counts[m];
    const int row0 = blockIdx.y * BM;
    if (row0 >= count) return;
    const int col0 = blockIdx.x * BN;      // over D=1024, always valid
    const int dhid = HDIM >> (NEXP - 1 - m);

    __shared__ __align__(16) float As[BK][BM + 4];
    __shared__ __align__(16) float Bs[BK][BN + 4];

    const int tid  = threadIdx.x;
    const int lrow = tid >> 2;
    const int lk4  = (tid & 3) * 4;

    const int arow = row0 + lrow;
    const bool avalid = (arow < count);
    const int tok_ld = avalid ? g_perm[m * T_TOT + arow] : 0;
    const float* aptr = g_h + (size_t)tok_ld * HDIM;
    const float* bptr = W2 + (size_t)(col0 + lrow) * HDIM;

    const int tx = tid & 15, ty = tid >> 4;
    float acc[4][4] = {};

    for (int k0 = 0; k0 < dhid; k0 += BK) {
        float4 av = avalid ? *(const float4*)(aptr + k0 + lk4)
                           : make_float4(0.f, 0.f, 0.f, 0.f);
        float4 bv = *(const float4*)(bptr + k0 + lk4);
        As[lk4 + 0][lrow] = av.x; As[lk4 + 1][lrow] = av.y;
        As[lk4 + 2][lrow] = av.z; As[lk4 + 3][lrow] = av.w;
        Bs[lk4 + 0][lrow] = bv.x; Bs[lk4 + 1][lrow] = bv.y;
        Bs[lk4 + 2][lrow] = bv.z; Bs[lk4 + 3][lrow] = bv.w;
        __syncthreads();
#pragma unroll
        for (int k = 0; k < BK; k++) {
            float4 a = *(const float4*)&As[k][ty * 4];
            float4 b = *(const float4*)&Bs[k][tx * 4];
            acc[0][0] += a.x * b.x; acc[0][1] += a.x * b.y; acc[0][2] += a.x * b.z; acc[0][3] += a.x * b.w;
            acc[1][0] += a.y * b.x; acc[1][1] += a.y * b.y; acc[1][2] += a.y * b.z; acc[1][3] += a.y * b.w;
            acc[2][0] += a.z * b.x; acc[2][1] += a.z * b.y; acc[2][2] += a.z * b.z; acc[2][3] += a.z * b.w;
            acc[3][0] += a.w * b.x; acc[3][1] += a.w * b.y; acc[3][2] += a.w * b.z; acc[3][3] += a.w * b.w;
        }
        __syncthreads();
    }

#pragma unroll
    for (int r = 0; r < 4; r++) {
        int grow = row0 + ty * 4 + r;
        if (grow < count) {
            int tok = g_perm[m * T_TOT + grow];
            float* orow = out + (size_t)tok * DDIM;
#pragma unroll
            for (int c = 0; c < 4; c++) {
                int d = col0 + tx * 4 + c;
                orow[d] = acc[r][c] + b2[d];
            }
        }
    }
}

// ---------------------------------------------------------------------------
// Launch
// inputs: 0:x [B,T,D] f32, 1:token_mask [B,T] i32, 2:W1 [H,D] f32,
//         3:b1 [H] f32, 4:W2 [D,H] f32, 5:b2 [D] f32 ; out: [B,T,D] f32
// ---------------------------------------------------------------------------
extern "C" void kernel_launch(void* const* d_in, const int* in_sizes, int n_in,
                              void* d_out, int out_size) {
    const float* x    = (const float*)d_in[0];
    const int*   mask = (const int*)  d_in[1];
    const float* W1   = (const float*)d_in[2];
    const float* b1   = (const float*)d_in[3];
    const float* W2   = (const float*)d_in[4];
    const float* b2   = (const float*)d_in[5];
    float* out = (float*)d_out;

    k_init_counts<<<1, 32>>>();
    k_scatter<<<(T_TOT + 255) / 256, 256>>>(mask);

    // GEMM1: N-tiles up to HDIM/BN = 64, M-tiles 256, 4 experts (most exit early)
    dim3 g1(HDIM / BN, T_TOT / BM, NEXP);
    k_gemm1<<<g1, 256>>>(x, W1, b1);

    // GEMM2: N = DDIM -> 16 tiles
    dim3 g2(DDIM / BN, T_TOT / BM, NEXP);
    k_gemm2<<<g2, 256>>>(W2, b2, out);
}

// round 12
// speedup vs baseline: 3.1513x; 3.1513x over previous
#include <cuda_runtime.h>
#include <math.h>
#include <stdint.h>

// Problem constants: B=4, T=4096, D=1024, H=4096, 4 nested experts
#define T_TOT 16384
#define DDIM  1024
#define HDIM  4096
#define NEXP  4

#define BM 128
#define BN 128
#define BK 32          // 32 fp32 per K chunk
#define ASTR 36        // smem row stride (floats): 32 + 4 pad -> conflict-free frags

__device__ int   g_counts[NEXP];
__device__ int   g_perm[NEXP * T_TOT];
__device__ float g_h[(size_t)T_TOT * HDIM];

// ---------------------------------------------------------------------------
// Helpers
// ---------------------------------------------------------------------------
__device__ __forceinline__ uint32_t to_tf32(float f) {
    uint32_t u;
    asm("cvt.rna.tf32.f32 %0, %1;" : "=r"(u) : "f"(f));
    return u;
}
__device__ __forceinline__ float gelu_exact(float v) {
    return 0.5f * v * (1.0f + erff(v * 0.70710678118654752f));
}
__device__ __forceinline__ void mma_tf32(float* c, const uint32_t* a, uint32_t b0, uint32_t b1) {
    asm volatile(
        "mma.sync.aligned.m16n8k8.row.col.f32.tf32.tf32.f32 "
        "{%0,%1,%2,%3}, {%4,%5,%6,%7}, {%8,%9}, {%0,%1,%2,%3};"
        : "+f"(c[0]), "+f"(c[1]), "+f"(c[2]), "+f"(c[3])
        : "r"(a[0]), "r"(a[1]), "r"(a[2]), "r"(a[3]), "r"(b0), "r"(b1));
}

// ---------------------------------------------------------------------------
// Expert grouping
// ---------------------------------------------------------------------------
__global__ void k_init_counts() {
    if (threadIdx.x < NEXP) g_counts[threadIdx.x] = 0;
}
__global__ void k_scatter(const int* __restrict__ mask) {
    int t = blockIdx.x * blockDim.x + threadIdx.x;
    if (t < T_TOT) {
        int e = mask[t];
        int pos = atomicAdd(&g_counts[e], 1);
        g_perm[e * T_TOT + pos] = t;
    }
}

// ---------------------------------------------------------------------------
// Shared TF32 mma.sync mainloop.
// A rows gathered via g_perm (tokens), B rows are weight rows (output cols).
// acc[mt][nt][4]: warp tile 32x64 = 2 m16 x 8 n8 mma tiles.
// ---------------------------------------------------------------------------
__device__ __forceinline__ void run_mainloop(
    float acc[2][8][4],
    uint32_t (*As)[ASTR], uint32_t (*Bs)[ASTR],
    int m, int count, int row0, int col0,
    const float* __restrict__ a_base, size_t a_stride,
    const float* __restrict__ b_base, size_t b_stride,
    int kdim)
{
    const int tid = threadIdx.x;
    const int wid = tid >> 5, lane = tid & 31;
    const int wm = wid & 3, wn = wid >> 2;
    const int g = lane >> 2, tg = lane & 3;

    // per-thread load slots: 1024 float4 per tile, thread t owns t, t+256, ...
    const float* aptr[4];
    const float* bptr[4];
    int rr_[4], c4_[4];
#pragma unroll
    for (int i = 0; i < 4; i++) {
        int s = tid + i * 256;
        int r = s >> 3, c4 = s & 7;
        rr_[i] = r; c4_[i] = c4;
        int arow = row0 + r;
        int pidx = (arow < count) ? arow : 0;
        int tok = g_perm[m * T_TOT + pidx];
        aptr[i] = a_base + (size_t)tok * a_stride + c4 * 4;
        bptr[i] = b_base + (size_t)(col0 + r) * b_stride + c4 * 4;
    }

    float4 pa[4], pb[4];
    const int nch = kdim / BK;

    // prologue load
#pragma unroll
    for (int i = 0; i < 4; i++) { pa[i] = *(const float4*)(aptr[i]); pb[i] = *(const float4*)(bptr[i]); }

    for (int c = 0; c < nch; c++) {
        // stage regs -> smem (with RNE tf32 conversion)
#pragma unroll
        for (int i = 0; i < 4; i++) {
            uint32_t* ar = &As[rr_[i]][c4_[i] * 4];
            ar[0] = to_tf32(pa[i].x); ar[1] = to_tf32(pa[i].y);
            ar[2] = to_tf32(pa[i].z); ar[3] = to_tf32(pa[i].w);
            uint32_t* br = &Bs[rr_[i]][c4_[i] * 4];
            br[0] = to_tf32(pb[i].x); br[1] = to_tf32(pb[i].y);
            br[2] = to_tf32(pb[i].z); br[3] = to_tf32(pb[i].w);
        }
        __syncthreads();

        // prefetch next chunk while computing this one
        if (c + 1 < nch) {
            int k0 = (c + 1) * BK;
#pragma unroll
            for (int i = 0; i < 4; i++) {
                pa[i] = *(const float4*)(aptr[i] + k0);
                pb[i] = *(const float4*)(bptr[i] + k0);
            }
        }

        // compute: 4 k-steps of 8
#pragma unroll
        for (int kk = 0; kk < 4; kk++) {
            const int kb = kk * 8;
            uint32_t af[2][4];
#pragma unroll
            for (int mt = 0; mt < 2; mt++) {
                int r = wm * 32 + mt * 16 + g;
                af[mt][0] = As[r][kb + tg];
                af[mt][1] = As[r + 8][kb + tg];
                af[mt][2] = As[r][kb + tg + 4];
                af[mt][3] = As[r + 8][kb + tg + 4];
            }
#pragma unroll
            for (int nt = 0; nt < 8; nt++) {
                int cc = wn * 64 + nt * 8 + g;
                uint32_t b0 = Bs[cc][kb + tg];
                uint32_t b1 = Bs[cc][kb + tg + 4];
                mma_tf32(acc[0][nt], af[0], b0, b1);
                mma_tf32(acc[1][nt], af[1], b0, b1);
            }
        }
        __syncthreads();
    }
}

// ---------------------------------------------------------------------------
// GEMM1: h = gelu(x @ W1^T + b1), nested slices, grouped by expert
// ---------------------------------------------------------------------------
__global__ void __launch_bounds__(256, 1) k_mma1(const float* __restrict__ x,
                                                 const float* __restrict__ W1,
                                                 const float* __restrict__ b1)
{
    const int m = blockIdx.z;
    const int count = g_counts[m];
    const int row0 = blockIdx.y * BM;
    if (row0 >= count) return;
    const int dhid = HDIM >> (NEXP - 1 - m);
    const int col0 = blockIdx.x * BN;
    if (col0 >= dhid) return;
    const int din = DDIM >> (NEXP - 1 - m);

    __shared__ uint32_t As[BM][ASTR];
    __shared__ uint32_t Bs[BN][ASTR];

    float acc[2][8][4] = {};
    run_mainloop(acc, As, Bs, m, count, row0, col0, x, DDIM, W1, DDIM, din);

    const int tid = threadIdx.x;
    const int wid = tid >> 5, lane = tid & 31;
    const int wm = wid & 3, wn = wid >> 2;
    const int g = lane >> 2, tg = lane & 3;

#pragma unroll
    for (int mt = 0; mt < 2; mt++) {
#pragma unroll
        for (int hr = 0; hr < 2; hr++) {
            int r = row0 + wm * 32 + mt * 16 + g + hr * 8;
            if (r < count) {
                int tok = g_perm[m * T_TOT + r];
                float* hrow = g_h + (size_t)tok * HDIM + col0;
#pragma unroll
                for (int nt = 0; nt < 8; nt++) {
                    int cc = wn * 64 + nt * 8 + tg * 2;
                    float v0 = acc[mt][nt][hr * 2 + 0] + b1[col0 + cc];
                    float v1 = acc[mt][nt][hr * 2 + 1] + b1[col0 + cc + 1];
                    hrow[cc]     = gelu_exact(v0);
                    hrow[cc + 1] = gelu_exact(v1);
                }
            }
        }
    }
}

// ---------------------------------------------------------------------------
// GEMM2: out = h @ W2^T + b2, K = nested dhid, grouped by expert
// ---------------------------------------------------------------------------
__global__ void __launch_bounds__(256, 1) k_mma2(const float* __restrict__ W2,
                                                 const float* __restrict__ b2,
                                                 float* __restrict__ out)
{
    const int m = blockIdx.z;
    const int count = g_counts[m];
    const int row0 = blockIdx.y * BM;
    if (row0 >= count) return;
    const int col0 = blockIdx.x * BN;          // N = DDIM, always valid
    const int dhid = HDIM >> (NEXP - 1 - m);

    __shared__ uint32_t As[BM][ASTR];
    __shared__ uint32_t Bs[BN][ASTR];

    float acc[2][8][4] = {};
    run_mainloop(acc, As, Bs, m, count, row0, col0, g_h, HDIM, W2, HDIM, dhid);

    const int tid = threadIdx.x;
    const int wid = tid >> 5, lane = tid & 31;
    const int wm = wid & 3, wn = wid >> 2;
    const int g = lane >> 2, tg = lane & 3;

#pragma unroll
    for (int mt = 0; mt < 2; mt++) {
#pragma unroll
        for (int hr = 0; hr < 2; hr++) {
            int r = row0 + wm * 32 + mt * 16 + g + hr * 8;
            if (r < count) {
                int tok = g_perm[m * T_TOT + r];
                float* orow = out + (size_t)tok * DDIM + col0;
#pragma unroll
                for (int nt = 0; nt < 8; nt++) {
                    int cc = wn * 64 + nt * 8 + tg * 2;
                    orow[cc]     = acc[mt][nt][hr * 2 + 0] + b2[col0 + cc];
                    orow[cc + 1] = acc[mt][nt][hr * 2 + 1] + b2[col0 + cc + 1];
                }
            }
        }
    }
}

// ---------------------------------------------------------------------------
// Launch
// inputs: 0:x [B,T,D] f32, 1:token_mask [B,T] i32, 2:W1 [H,D] f32,
//         3:b1 [H] f32, 4:W2 [D,H] f32, 5:b2 [D] f32 ; out [B,T,D] f32
// ---------------------------------------------------------------------------
extern "C" void kernel_launch(void* const* d_in, const int* in_sizes, int n_in,
                              void* d_out, int out_size) {
    const float* x    = (const float*)d_in[0];
    const int*   mask = (const int*)  d_in[1];
    const float* W1   = (const float*)d_in[2];
    const float* b1   = (const float*)d_in[3];
    const float* W2   = (const float*)d_in[4];
    const float* b2   = (const float*)d_in[5];
    float* out = (float*)d_out;

    k_init_counts<<<1, 32>>>();
    k_scatter<<<(T_TOT + 255) / 256, 256>>>(mask);

    dim3 g1(HDIM / BN, T_TOT / BM, NEXP);   // 32 x 128 x 4 (most blocks exit early)
    k_mma1<<<g1, 256>>>(x, W1, b1);

    dim3 g2(DDIM / BN, T_TOT / BM, NEXP);   // 8 x 128 x 4
    k_mma2<<<g2, 256>>>(W2, b2, out);
}

// round 13
// speedup vs baseline: 3.6589x; 1.1611x over previous
#include <cuda_runtime.h>
#include <math.h>
#include <stdint.h>

// Problem constants: B=4, T=4096, D=1024, H=4*D, 4 nested experts
#define T_TOT 16384
#define DDIM  1024
#define HDIM  4096
#define NEXP  4

#define BM 128
#define BN 128
#define BK 32          // K chunk (fp32 elements)
#define ASTR 36        // smem row stride in floats (32+4 pad -> conflict-free frags)

#define STG_FLOATS ((BM + BN) * ASTR)       // 9216 floats per stage
#define STG_BYTES  (STG_FLOATS * 4)         // 36864 B
#define SMEM_TOTAL (2 * STG_BYTES)          // 73728 B (double buffered)

__device__ int   g_counts[NEXP];
__device__ int   g_perm[NEXP * T_TOT];
__device__ float g_h [(size_t)T_TOT * HDIM];   // 256 MB, tf32-rounded at write
__device__ float g_xc[(size_t)T_TOT * DDIM];   // 64 MB, tf32-rounded x
__device__ float g_w1[(size_t)HDIM * DDIM];    // 16 MB
__device__ float g_w2[(size_t)DDIM * HDIM];    // 16 MB

// ---------------------------------------------------------------------------
// Helpers
// ---------------------------------------------------------------------------
__device__ __forceinline__ uint32_t smem_u32(const void* p) {
    uint32_t a;
    asm("{ .reg .u64 t; cvta.to.shared.u64 t, %1; cvt.u32.u64 %0, t; }" : "=r"(a) : "l"(p));
    return a;
}
__device__ __forceinline__ uint32_t to_tf32(float f) {
    uint32_t u;
    asm("cvt.rna.tf32.f32 %0, %1;" : "=r"(u) : "f"(f));
    return u;
}
__device__ __forceinline__ float gelu_exact(float v) {
    return 0.5f * v * (1.0f + erff(v * 0.70710678118654752f));
}
__device__ __forceinline__ void mma_tf32(float* c, const uint32_t* a, uint32_t b0, uint32_t b1) {
    asm volatile(
        "mma.sync.aligned.m16n8k8.row.col.f32.tf32.tf32.f32 "
        "{%0,%1,%2,%3}, {%4,%5,%6,%7}, {%8,%9}, {%0,%1,%2,%3};"
        : "+f"(c[0]), "+f"(c[1]), "+f"(c[2]), "+f"(c[3])
        : "r"(a[0]), "r"(a[1]), "r"(a[2]), "r"(a[3]), "r"(b0), "r"(b1));
}
__device__ __forceinline__ void cp16(uint32_t dst, const void* src) {
    asm volatile("cp.async.cg.shared.global [%0], [%1], 16;" :: "r"(dst), "l"(src) : "memory");
}
__device__ __forceinline__ void cp_commit() { asm volatile("cp.async.commit_group;" ::: "memory"); }
__device__ __forceinline__ void cp_wait1()  { asm volatile("cp.async.wait_group 1;" ::: "memory"); }
__device__ __forceinline__ void cp_wait0()  { asm volatile("cp.async.wait_group 0;" ::: "memory"); }

// ---------------------------------------------------------------------------
// Pre-round to TF32 (RNE via cvt.rna) — one-time, HBM-bound
// ---------------------------------------------------------------------------
__global__ void k_cvt(const float4* __restrict__ in, float4* __restrict__ outp, int n4) {
    int i = blockIdx.x * blockDim.x + threadIdx.x;
    if (i < n4) {
        float4 v = in[i];
        float4 o;
        o.x = __uint_as_float(to_tf32(v.x));
        o.y = __uint_as_float(to_tf32(v.y));
        o.z = __uint_as_float(to_tf32(v.z));
        o.w = __uint_as_float(to_tf32(v.w));
        outp[i] = o;
    }
}

// ---------------------------------------------------------------------------
// Expert grouping
// ---------------------------------------------------------------------------
__global__ void k_init_counts() {
    if (threadIdx.x < NEXP) g_counts[threadIdx.x] = 0;
}
__global__ void k_scatter(const int* __restrict__ mask) {
    int t = blockIdx.x * blockDim.x + threadIdx.x;
    if (t < T_TOT) {
        int e = mask[t];
        int pos = atomicAdd(&g_counts[e], 1);
        g_perm[e * T_TOT + pos] = t;
    }
}

// ---------------------------------------------------------------------------
// Shared mainloop: cp.async double-buffered staging of pre-rounded data,
// mma.sync.tf32 compute. A rows gathered via g_perm; B rows = weight rows.
// ---------------------------------------------------------------------------
__device__ __forceinline__ void run_mainloop(
    float acc[2][8][4], const float* smem, uint32_t sbase,
    int m, int count, int row0, int col0,
    const float* __restrict__ a_base, size_t a_stride,
    const float* __restrict__ b_base, size_t b_stride,
    int kdim)
{
    const int tid = threadIdx.x;
    const int lane = tid & 31, wid = tid >> 5;
    const int wm = wid & 3, wn = wid >> 2;
    const int g = lane >> 2, tg = lane & 3;

    // 8 cp.async slots per thread: 4 for A (1024 float4), 4 for B
    const float* gsrc[8];
    uint32_t sdst[8];
#pragma unroll
    for (int i = 0; i < 4; i++) {
        int s = tid + i * 256;
        int r = s >> 3, c4 = s & 7;
        int arow = row0 + r;
        int pidx = (arow < count) ? arow : 0;
        int tok = g_perm[m * T_TOT + pidx];
        gsrc[i] = a_base + (size_t)tok * a_stride + c4 * 4;
        sdst[i] = sbase + (uint32_t)(r * ASTR + c4 * 4) * 4u;
        gsrc[i + 4] = b_base + (size_t)(col0 + r) * b_stride + c4 * 4;
        sdst[i + 4] = sbase + (uint32_t)((BM + r) * ASTR + c4 * 4) * 4u;
    }

    const int nch = kdim / BK;
    // prologue: chunk 0 -> stage 0
#pragma unroll
    for (int i = 0; i < 8; i++) cp16(sdst[i], gsrc[i]);
    cp_commit();

    for (int c = 0; c < nch; c++) {
        if (c + 1 < nch) {
            const uint32_t bo = (uint32_t)((c + 1) & 1) * STG_BYTES;
            const int k0 = (c + 1) * BK;
#pragma unroll
            for (int i = 0; i < 8; i++) cp16(sdst[i] + bo, gsrc[i] + k0);
            cp_commit();
            cp_wait1();
        } else {
            cp_wait0();
        }
        __syncthreads();

        const float* A = smem + (c & 1) * STG_FLOATS;
        const float* B = A + BM * ASTR;

#pragma unroll
        for (int kk = 0; kk < 4; kk++) {
            const int kb = kk * 8;
            uint32_t af[2][4];
#pragma unroll
            for (int mt = 0; mt < 2; mt++) {
                int r = wm * 32 + mt * 16 + g;
                af[mt][0] = __float_as_uint(A[r * ASTR + kb + tg]);
                af[mt][1] = __float_as_uint(A[(r + 8) * ASTR + kb + tg]);
                af[mt][2] = __float_as_uint(A[r * ASTR + kb + tg + 4]);
                af[mt][3] = __float_as_uint(A[(r + 8) * ASTR + kb + tg + 4]);
            }
#pragma unroll
            for (int nt = 0; nt < 8; nt++) {
                int cc = wn * 64 + nt * 8 + g;
                uint32_t b0 = __float_as_uint(B[cc * ASTR + kb + tg]);
                uint32_t b1 = __float_as_uint(B[cc * ASTR + kb + tg + 4]);
                mma_tf32(acc[0][nt], af[0], b0, b1);
                mma_tf32(acc[1][nt], af[1], b0, b1);
            }
        }
        __syncthreads();   // reads of stage (c&1) done before iter c+1 overwrites it
    }
}

// ---------------------------------------------------------------------------
// GEMM1: h = tf32round(gelu(x @ W1^T + b1)), nested slices, grouped by expert
// ---------------------------------------------------------------------------
__global__ void __launch_bounds__(256, 2) k_mma1(const float* __restrict__ b1)
{
    const int m = blockIdx.z;
    const int count = g_counts[m];
    const int row0 = blockIdx.y * BM;
    if (row0 >= count) return;
    const int dhid = HDIM >> (NEXP - 1 - m);
    const int col0 = blockIdx.x * BN;
    if (col0 >= dhid) return;
    const int din = DDIM >> (NEXP - 1 - m);

    extern __shared__ __align__(16) float smem[];
    uint32_t sbase = smem_u32(smem);

    float acc[2][8][4] = {};
    run_mainloop(acc, smem, sbase, m, count, row0, col0, g_xc, DDIM, g_w1, DDIM, din);

    const int tid = threadIdx.x;
    const int lane = tid & 31, wid = tid >> 5;
    const int wm = wid & 3, wn = wid >> 2;
    const int g = lane >> 2, tg = lane & 3;

#pragma unroll
    for (int mt = 0; mt < 2; mt++) {
#pragma unroll
        for (int hr = 0; hr < 2; hr++) {
            int r = row0 + wm * 32 + mt * 16 + g + hr * 8;
            if (r < count) {
                int tok = g_perm[m * T_TOT + r];
                float* hrow = g_h + (size_t)tok * HDIM + col0;
#pragma unroll
                for (int nt = 0; nt < 8; nt++) {
                    int cc = wn * 64 + nt * 8 + tg * 2;
                    float v0 = acc[mt][nt][hr * 2 + 0] + b1[col0 + cc];
                    float v1 = acc[mt][nt][hr * 2 + 1] + b1[col0 + cc + 1];
                    hrow[cc]     = __uint_as_float(to_tf32(gelu_exact(v0)));
                    hrow[cc + 1] = __uint_as_float(to_tf32(gelu_exact(v1)));
                }
            }
        }
    }
}

// ---------------------------------------------------------------------------
// GEMM2: out = h @ W2^T + b2, K = nested dhid, grouped by expert
// ---------------------------------------------------------------------------
__global__ void __launch_bounds__(256, 2) k_mma2(const float* __restrict__ b2,
                                                 float* __restrict__ out)
{
    const int m = blockIdx.z;
    const int count = g_counts[m];
    const int row0 = blockIdx.y * BM;
    if (row0 >= count) return;
    const int col0 = blockIdx.x * BN;          // N = DDIM, always valid
    const int dhid = HDIM >> (NEXP - 1 - m);

    extern __shared__ __align__(16) float smem[];
    uint32_t sbase = smem_u32(smem);

    float acc[2][8][4] = {};
    run_mainloop(acc, smem, sbase, m, count, row0, col0, g_h, HDIM, g_w2, HDIM, dhid);

    const int tid = threadIdx.x;
    const int lane = tid & 31, wid = tid >> 5;
    const int wm = wid & 3, wn = wid >> 2;
    const int g = lane >> 2, tg = lane & 3;

#pragma unroll
    for (int mt = 0; mt < 2; mt++) {
#pragma unroll
        for (int hr = 0; hr < 2; hr++) {
            int r = row0 + wm * 32 + mt * 16 + g + hr * 8;
            if (r < count) {
                int tok = g_perm[m * T_TOT + r];
                float* orow = out + (size_t)tok * DDIM + col0;
#pragma unroll
                for (int nt = 0; nt < 8; nt++) {
                    int cc = wn * 64 + nt * 8 + tg * 2;
                    orow[cc]     = acc[mt][nt][hr * 2 + 0] + b2[col0 + cc];
                    orow[cc + 1] = acc[mt][nt][hr * 2 + 1] + b2[col0 + cc + 1];
                }
            }
        }
    }
}

// ---------------------------------------------------------------------------
// Launch
// inputs: 0:x [B,T,D] f32, 1:token_mask [B,T] i32, 2:W1 [H,D] f32,
//         3:b1 [H] f32, 4:W2 [D,H] f32, 5:b2 [D] f32 ; out [B,T,D] f32
// ---------------------------------------------------------------------------
extern "C" void kernel_launch(void* const* d_in, const int* in_sizes, int n_in,
                              void* d_out, int out_size) {
    const float* x    = (const float*)d_in[0];
    const int*   mask = (const int*)  d_in[1];
    const float* W1   = (const float*)d_in[2];
    const float* b1   = (const float*)d_in[3];
    const float* W2   = (const float*)d_in[4];
    const float* b2   = (const float*)d_in[5];
    float* out = (float*)d_out;

    static int attr_done = 0;
    if (!attr_done) {
        cudaFuncSetAttribute(k_mma1, cudaFuncAttributeMaxDynamicSharedMemorySize, SMEM_TOTAL);
        cudaFuncSetAttribute(k_mma2, cudaFuncAttributeMaxDynamicSharedMemorySize, SMEM_TOTAL);
        attr_done = 1;
    }

    // Resolve __device__ globals into kernel-arg pointers? Not needed: kernels
    // reference the globals directly; cvt kernels get raw input pointers.
    float* xc; cudaGetSymbolAddress((void**)&xc, g_xc);
    float* w1; cudaGetSymbolAddress((void**)&w1, g_w1);
    float* w2; cudaGetSymbolAddress((void**)&w2, g_w2);

    const int NX = T_TOT * DDIM / 4, NW1 = HDIM * DDIM / 4, NW2 = DDIM * HDIM / 4;
    k_cvt<<<(NX  + 255) / 256, 256>>>((const float4*)x,  (float4*)xc, NX);
    k_cvt<<<(NW1 + 255) / 256, 256>>>((const float4*)W1, (float4*)w1, NW1);
    k_cvt<<<(NW2 + 255) / 256, 256>>>((const float4*)W2, (float4*)w2, NW2);

    k_init_counts<<<1, 32>>>();
    k_scatter<<<(T_TOT + 255) / 256, 256>>>(mask);

    dim3 g1(HDIM / BN, T_TOT / BM, NEXP);   // most blocks exit early per nesting
    k_mma1<<<g1, 256, SMEM_TOTAL>>>(b1);

    dim3 g2(DDIM / BN, T_TOT / BM, NEXP);
    k_mma2<<<g2, 256, SMEM_TOTAL>>>(b2, out);
}

// round 15
// speedup vs baseline: 6.4878x; 1.7731x over previous
#include <cuda_runtime.h>
#include <cuda_fp16.h>
#include <math.h>
#include <stdint.h>

// Problem constants: B=4, T=4096, D=1024, H=4*D, 4 nested experts
#define T_TOT 16384
#define DDIM  1024
#define HDIM  4096
#define NEXP  4

#define BM 128
#define BN 128
#define BK 64          // K chunk in halves (4 k-steps of m16n8k16)
#define HSTR 72        // smem row stride in halves (64 data + 8 pad -> conflict-free)

#define STG_HALVES ((BM + BN) * HSTR)       // 18432 halves / stage
#define STG_BYTES  (STG_HALVES * 2)         // 36864 B
#define SMEM_TOTAL (2 * STG_BYTES)          // 73728 B (double buffered)

__device__ int    g_counts[NEXP];
__device__ int    g_perm[NEXP * T_TOT];
__device__ __align__(256) __half g_h [(size_t)T_TOT * HDIM];   // 128 MB hidden (fp16)
__device__ __align__(256) __half g_xh[(size_t)T_TOT * DDIM];   // 32 MB x (fp16)
__device__ __align__(256) __half g_w1[(size_t)HDIM * DDIM];    // 8 MB
__device__ __align__(256) __half g_w2[(size_t)DDIM * HDIM];    // 8 MB

// ---------------------------------------------------------------------------
// Helpers
// ---------------------------------------------------------------------------
__device__ __forceinline__ uint32_t smem_u32(const void* p) {
    uint32_t a;
    asm("{ .reg .u64 t; cvta.to.shared.u64 t, %1; cvt.u32.u64 %0, t; }" : "=r"(a) : "l"(p));
    return a;
}
__device__ __forceinline__ float gelu_exact(float v) {
    return 0.5f * v * (1.0f + erff(v * 0.70710678118654752f));
}
__device__ __forceinline__ void mma_f16(float* c, const uint32_t* a, uint32_t b0, uint32_t b1) {
    asm volatile(
        "mma.sync.aligned.m16n8k16.row.col.f32.f16.f16.f32 "
        "{%0,%1,%2,%3}, {%4,%5,%6,%7}, {%8,%9}, {%0,%1,%2,%3};"
        : "+f"(c[0]), "+f"(c[1]), "+f"(c[2]), "+f"(c[3])
        : "r"(a[0]), "r"(a[1]), "r"(a[2]), "r"(a[3]), "r"(b0), "r"(b1));
}
__device__ __forceinline__ void cp16(uint32_t dst, const void* src) {
    asm volatile("cp.async.cg.shared.global [%0], [%1], 16;" :: "r"(dst), "l"(src) : "memory");
}
__device__ __forceinline__ void cp_commit() { asm volatile("cp.async.commit_group;" ::: "memory"); }
__device__ __forceinline__ void cp_wait1()  { asm volatile("cp.async.wait_group 1;" ::: "memory"); }
__device__ __forceinline__ void cp_wait0()  { asm volatile("cp.async.wait_group 0;" ::: "memory"); }

// ---------------------------------------------------------------------------
// fp32 -> fp16 conversion (RNE), vectorized
// ---------------------------------------------------------------------------
__global__ void k_cvt_h(const float4* __restrict__ in, uint2* __restrict__ outp, int n4) {
    int i = blockIdx.x * blockDim.x + threadIdx.x;
    if (i < n4) {
        float4 v = in[i];
        __half2 lo = __floats2half2_rn(v.x, v.y);
        __half2 hi = __floats2half2_rn(v.z, v.w);
        uint2 o;
        o.x = *(const uint32_t*)&lo;
        o.y = *(const uint32_t*)&hi;
        outp[i] = o;
    }
}

// ---------------------------------------------------------------------------
// Expert grouping
// ---------------------------------------------------------------------------
__global__ void k_init_counts() {
    if (threadIdx.x < NEXP) g_counts[threadIdx.x] = 0;
}
__global__ void k_scatter(const int* __restrict__ mask) {
    int t = blockIdx.x * blockDim.x + threadIdx.x;
    if (t < T_TOT) {
        int e = mask[t];
        int pos = atomicAdd(&g_counts[e], 1);
        g_perm[e * T_TOT + pos] = t;
    }
}

// ---------------------------------------------------------------------------
// Shared mainloop: cp.async double-buffered fp16 staging, m16n8k16 HMMA.
// A rows gathered via g_perm; B rows = weight rows (output columns).
// ---------------------------------------------------------------------------
__device__ __forceinline__ void run_mainloop(
    float acc[2][8][4], const __half* smem, uint32_t sbase,
    int m, int count, int row0, int col0,
    const __half* __restrict__ a_base, size_t a_stride,
    const __half* __restrict__ b_base, size_t b_stride,
    int kdim)
{
    const int tid = threadIdx.x;
    const int lane = tid & 31, wid = tid >> 5;
    const int wm = wid & 3, wn = wid >> 2;
    const int g = lane >> 2, tg = lane & 3;

    // 8 cp.async slots/thread: A rows 128 x 8 x 16B, B same
    const __half* gsrc[8];
    uint32_t sdst[8];
#pragma unroll
    for (int i = 0; i < 4; i++) {
        int s = tid + i * 256;
        int r = s >> 3, c = s & 7;                 // c: 16B slot (8 halves)
        int arow = row0 + r;
        int pidx = (arow < count) ? arow : 0;
        int tok = g_perm[m * T_TOT + pidx];
        gsrc[i] = a_base + (size_t)tok * a_stride + c * 8;
        sdst[i] = sbase + (uint32_t)(r * HSTR + c * 8) * 2u;
        gsrc[i + 4] = b_base + (size_t)(col0 + r) * b_stride + c * 8;
        sdst[i + 4] = sbase + (uint32_t)((BM + r) * HSTR + c * 8) * 2u;
    }

    const int nch = kdim / BK;

#pragma unroll
    for (int i = 0; i < 8; i++) cp16(sdst[i], gsrc[i]);
    cp_commit();

    for (int c = 0; c < nch; c++) {
        if (c + 1 < nch) {
            const uint32_t bo = (uint32_t)((c + 1) & 1) * STG_BYTES;
            const int k0 = (c + 1) * BK;
#pragma unroll
            for (int i = 0; i < 8; i++) cp16(sdst[i] + bo, gsrc[i] + k0);
            cp_commit();
            cp_wait1();
        } else {
            cp_wait0();
        }
        __syncthreads();

        const __half* A = smem + (c & 1) * STG_HALVES;
        const __half* B = A + BM * HSTR;

#pragma unroll
        for (int kk = 0; kk < 4; kk++) {
            const int kb = kk * 16;
            uint32_t af[2][4];
#pragma unroll
            for (int mt = 0; mt < 2; mt++) {
                int r = wm * 32 + mt * 16 + g;
                af[mt][0] = *(const uint32_t*)(A + r * HSTR + kb + 2 * tg);
                af[mt][1] = *(const uint32_t*)(A + (r + 8) * HSTR + kb + 2 * tg);
                af[mt][2] = *(const uint32_t*)(A + r * HSTR + kb + 2 * tg + 8);
                af[mt][3] = *(const uint32_t*)(A + (r + 8) * HSTR + kb + 2 * tg + 8);
            }
#pragma unroll
            for (int nt = 0; nt < 8; nt++) {
                int cc = wn * 64 + nt * 8 + g;
                uint32_t b0 = *(const uint32_t*)(B + cc * HSTR + kb + 2 * tg);
                uint32_t b1 = *(const uint32_t*)(B + cc * HSTR + kb + 2 * tg + 8);
                mma_f16(acc[0][nt], af[0], b0, b1);
                mma_f16(acc[1][nt], af[1], b0, b1);
            }
        }
        __syncthreads();
    }
}

// ---------------------------------------------------------------------------
// GEMM1: h = fp16(gelu(x @ W1^T + b1)), nested slices, grouped by expert
// ---------------------------------------------------------------------------
__global__ void __launch_bounds__(256, 2) k_mma1(const float* __restrict__ b1)
{
    const int m = blockIdx.z;
    const int count = g_counts[m];
    const int row0 = blockIdx.y * BM;
    if (row0 >= count) return;
    const int dhid = HDIM >> (NEXP - 1 - m);
    const int col0 = blockIdx.x * BN;
    if (col0 >= dhid) return;
    const int din = DDIM >> (NEXP - 1 - m);

    extern __shared__ __align__(16) __half smem[];
    uint32_t sbase = smem_u32(smem);

    float acc[2][8][4] = {};
    run_mainloop(acc, smem, sbase, m, count, row0, col0, g_xh, DDIM, g_w1, DDIM, din);

    const int tid = threadIdx.x;
    const int lane = tid & 31, wid = tid >> 5;
    const int wm = wid & 3, wn = wid >> 2;
    const int g = lane >> 2, tg = lane & 3;

#pragma unroll
    for (int mt = 0; mt < 2; mt++) {
#pragma unroll
        for (int hr = 0; hr < 2; hr++) {
            int r = row0 + wm * 32 + mt * 16 + g + hr * 8;
            if (r < count) {
                int tok = g_perm[m * T_TOT + r];
                __half* hrow = g_h + (size_t)tok * HDIM + col0;
#pragma unroll
                for (int nt = 0; nt < 8; nt++) {
                    int cc = wn * 64 + nt * 8 + tg * 2;
                    float v0 = gelu_exact(acc[mt][nt][hr * 2 + 0] + b1[col0 + cc]);
                    float v1 = gelu_exact(acc[mt][nt][hr * 2 + 1] + b1[col0 + cc + 1]);
                    *(__half2*)(hrow + cc) = __floats2half2_rn(v0, v1);
                }
            }
        }
    }
}

// ---------------------------------------------------------------------------
// GEMM2: out = h @ W2^T + b2 (fp32 out), K = nested dhid, grouped by expert
// ---------------------------------------------------------------------------
__global__ void __launch_bounds__(256, 2) k_mma2(const float* __restrict__ b2,
                                                 float* __restrict__ out)
{
    const int m = blockIdx.z;
    const int count = g_counts[m];
    const int row0 = blockIdx.y * BM;
    if (row0 >= count) return;
    const int col0 = blockIdx.x * BN;          // N = DDIM, always valid
    const int dhid = HDIM >> (NEXP - 1 - m);

    extern __shared__ __align__(16) __half smem[];
    uint32_t sbase = smem_u32(smem);

    float acc[2][8][4] = {};
    run_mainloop(acc, smem, sbase, m, count, row0, col0, g_h, HDIM, g_w2, HDIM, dhid);

    const int tid = threadIdx.x;
    const int lane = tid & 31, wid = tid >> 5;
    const int wm = wid & 3, wn = wid >> 2;
    const int g = lane >> 2, tg = lane & 3;

#pragma unroll
    for (int mt = 0; mt < 2; mt++) {
#pragma unroll
        for (int hr = 0; hr < 2; hr++) {
            int r = row0 + wm * 32 + mt * 16 + g + hr * 8;
            if (r < count) {
                int tok = g_perm[m * T_TOT + r];
                float* orow = out + (size_t)tok * DDIM + col0;
#pragma unroll
                for (int nt = 0; nt < 8; nt++) {
                    int cc = wn * 64 + nt * 8 + tg * 2;
                    orow[cc]     = acc[mt][nt][hr * 2 + 0] + b2[col0 + cc];
                    orow[cc + 1] = acc[mt][nt][hr * 2 + 1] + b2[col0 + cc + 1];
                }
            }
        }
    }
}

// ---------------------------------------------------------------------------
// Launch
// inputs: 0:x [B,T,D] f32, 1:token_mask [B,T] i32, 2:W1 [H,D] f32,
//         3:b1 [H] f32, 4:W2 [D,H] f32, 5:b2 [D] f32 ; out [B,T,D] f32
// ---------------------------------------------------------------------------
extern "C" void kernel_launch(void* const* d_in, const int* in_sizes, int n_in,
                              void* d_out, int out_size) {
    const float* x    = (const float*)d_in[0];
    const int*   mask = (const int*)  d_in[1];
    const float* W1   = (const float*)d_in[2];
    const float* b1   = (const float*)d_in[3];
    const float* W2   = (const float*)d_in[4];
    const float* b2   = (const float*)d_in[5];
    float* out = (float*)d_out;

    static int attr_done = 0;
    if (!attr_done) {
        cudaFuncSetAttribute(k_mma1, cudaFuncAttributeMaxDynamicSharedMemorySize, SMEM_TOTAL);
        cudaFuncSetAttribute(k_mma2, cudaFuncAttributeMaxDynamicSharedMemorySize, SMEM_TOTAL);
        attr_done = 1;
    }

    void* xh; cudaGetSymbolAddress(&xh, g_xh);
    void* w1; cudaGetSymbolAddress(&w1, g_w1);
    void* w2; cudaGetSymbolAddress(&w2, g_w2);

    const int NX = T_TOT * DDIM / 4, NW1 = HDIM * DDIM / 4, NW2 = DDIM * HDIM / 4;
    k_cvt_h<<<(NX  + 255) / 256, 256>>>((const float4*)x,  (uint2*)xh, NX);
    k_cvt_h<<<(NW1 + 255) / 256, 256>>>((const float4*)W1, (uint2*)w1, NW1);
    k_cvt_h<<<(NW2 + 255) / 256, 256>>>((const float4*)W2, (uint2*)w2, NW2);

    k_init_counts<<<1, 32>>>();
    k_scatter<<<(T_TOT + 255) / 256, 256>>>(mask);

    dim3 g1(HDIM / BN, T_TOT / BM, NEXP);   // most blocks exit early per nesting
    k_mma1<<<g1, 256, SMEM_TOTAL>>>(b1);

    dim3 g2(DDIM / BN, T_TOT / BM, NEXP);
    k_mma2<<<g2, 256, SMEM_TOTAL>>>(b2, out);
}

// round 16
// speedup vs baseline: 7.0154x; 1.0813x over previous
#include <cuda_runtime.h>
#include <cuda_fp16.h>
#include <math.h>
#include <stdint.h>

// Problem constants: B=4, T=4096, D=1024, H=4*D, 4 nested experts
#define T_TOT 16384
#define DDIM  1024
#define HDIM  4096
#define NEXP  4

#define BM 128
#define BN 128
#define BK 64          // K chunk in halves (4 k-steps of m16n8k16)
#define HSTR 72        // smem row stride in halves (64 data + 8 pad -> conflict-free)
#define NSTAGE 3

#define STG_HALVES ((BM + BN) * HSTR)       // 18432 halves / stage
#define STG_BYTES  (STG_HALVES * 2)         // 36864 B
#define SMEM_TOTAL (NSTAGE * STG_BYTES)     // 110592 B (3-stage)

__device__ int    g_counts[NEXP];
__device__ int    g_perm[NEXP * T_TOT];
__device__ __align__(256) __half g_h [(size_t)T_TOT * HDIM];   // 128 MB hidden (fp16)
__device__ __align__(256) __half g_xh[(size_t)T_TOT * DDIM];   // 32 MB x (fp16)
__device__ __align__(256) __half g_w1[(size_t)HDIM * DDIM];    // 8 MB
__device__ __align__(256) __half g_w2[(size_t)DDIM * HDIM];    // 8 MB

// ---------------------------------------------------------------------------
// Helpers
// ---------------------------------------------------------------------------
__device__ __forceinline__ uint32_t smem_u32(const void* p) {
    uint32_t a;
    asm("{ .reg .u64 t; cvta.to.shared.u64 t, %1; cvt.u32.u64 %0, t; }" : "=r"(a) : "l"(p));
    return a;
}
__device__ __forceinline__ float gelu_exact(float v) {
    return 0.5f * v * (1.0f + erff(v * 0.70710678118654752f));
}
__device__ __forceinline__ void mma_f16(float* c, const uint32_t* a, uint32_t b0, uint32_t b1) {
    asm volatile(
        "mma.sync.aligned.m16n8k16.row.col.f32.f16.f16.f32 "
        "{%0,%1,%2,%3}, {%4,%5,%6,%7}, {%8,%9}, {%0,%1,%2,%3};"
        : "+f"(c[0]), "+f"(c[1]), "+f"(c[2]), "+f"(c[3])
        : "r"(a[0]), "r"(a[1]), "r"(a[2]), "r"(a[3]), "r"(b0), "r"(b1));
}
__device__ __forceinline__ void ldm_x4(uint32_t& r0, uint32_t& r1, uint32_t& r2, uint32_t& r3,
                                       uint32_t addr) {
    asm volatile("ldmatrix.sync.aligned.m8n8.x4.shared.b16 {%0,%1,%2,%3}, [%4];"
                 : "=r"(r0), "=r"(r1), "=r"(r2), "=r"(r3) : "r"(addr));
}
__device__ __forceinline__ void cp16(uint32_t dst, const void* src) {
    asm volatile("cp.async.cg.shared.global [%0], [%1], 16;" :: "r"(dst), "l"(src) : "memory");
}
__device__ __forceinline__ void cp_commit() { asm volatile("cp.async.commit_group;" ::: "memory"); }
__device__ __forceinline__ void cp_wait2()  { asm volatile("cp.async.wait_group 2;" ::: "memory"); }

// ---------------------------------------------------------------------------
// fp32 -> fp16 conversion (RNE), vectorized
// ---------------------------------------------------------------------------
__global__ void k_cvt_h(const float4* __restrict__ in, uint2* __restrict__ outp, int n4) {
    int i = blockIdx.x * blockDim.x + threadIdx.x;
    if (i < n4) {
        float4 v = in[i];
        __half2 lo = __floats2half2_rn(v.x, v.y);
        __half2 hi = __floats2half2_rn(v.z, v.w);
        uint2 o;
        o.x = *(const uint32_t*)&lo;
        o.y = *(const uint32_t*)&hi;
        outp[i] = o;
    }
}

// ---------------------------------------------------------------------------
// Expert grouping
// ---------------------------------------------------------------------------
__global__ void k_init_counts() {
    if (threadIdx.x < NEXP) g_counts[threadIdx.x] = 0;
}
__global__ void k_scatter(const int* __restrict__ mask) {
    int t = blockIdx.x * blockDim.x + threadIdx.x;
    if (t < T_TOT) {
        int e = mask[t];
        int pos = atomicAdd(&g_counts[e], 1);
        g_perm[e * T_TOT + pos] = t;
    }
}

// ---------------------------------------------------------------------------
// Shared mainloop: 3-stage cp.async fp16 staging, ldmatrix.x4 fragments,
// m16n8k16 HMMA. A rows gathered via g_perm; B rows = weight rows.
// ---------------------------------------------------------------------------
__device__ __forceinline__ void run_mainloop(
    float acc[2][8][4], uint32_t sbase,
    int m, int count, int row0, int col0,
    const __half* __restrict__ a_base, size_t a_stride,
    const __half* __restrict__ b_base, size_t b_stride,
    int kdim)
{
    const int tid = threadIdx.x;
    const int lane = tid & 31, wid = tid >> 5;
    const int wm = wid & 3, wn = wid >> 2;

    // 8 cp.async slots/thread: A rows 128 x 8 x 16B, B same
    const __half* gsrc[8];
    uint32_t sdst[8];
#pragma unroll
    for (int i = 0; i < 4; i++) {
        int s = tid + i * 256;
        int r = s >> 3, c = s & 7;                 // c: 16B slot (8 halves)
        int arow = row0 + r;
        int pidx = (arow < count) ? arow : 0;
        int tok = g_perm[m * T_TOT + pidx];
        gsrc[i] = a_base + (size_t)tok * a_stride + c * 8;
        sdst[i] = sbase + (uint32_t)(r * HSTR + c * 8) * 2u;
        gsrc[i + 4] = b_base + (size_t)(col0 + r) * b_stride + c * 8;
        sdst[i + 4] = sbase + (uint32_t)((BM + r) * HSTR + c * 8) * 2u;
    }

    // ldmatrix per-lane base offsets (bytes within a stage)
    const uint32_t a_off = 2u * ((uint32_t)(wm * 32 + (lane & 15)) * HSTR + (uint32_t)(lane >> 4) * 8);
    const uint32_t b_off = 2u * ((uint32_t)(BM + wn * 64 + ((lane >> 4) & 1) * 8 + (lane & 7)) * HSTR
                                 + (uint32_t)((lane >> 3) & 1) * 8);

    const int nch = kdim / BK;

    // prologue: chunks 0,1 -> stages 0,1
#pragma unroll
    for (int i = 0; i < 8; i++) cp16(sdst[i], gsrc[i]);
    cp_commit();
    if (nch > 1) {
#pragma unroll
        for (int i = 0; i < 8; i++) cp16(sdst[i] + STG_BYTES, gsrc[i] + BK);
    }
    cp_commit();

    int st_issue = 2;   // stage for chunk c+2
    int st_comp = 0;    // stage for chunk c
    for (int c = 0; c < nch; c++) {
        if (c + 2 < nch) {
            const uint32_t bo = (uint32_t)st_issue * STG_BYTES;
            const int k0 = (c + 2) * BK;
#pragma unroll
            for (int i = 0; i < 8; i++) cp16(sdst[i] + bo, gsrc[i] + k0);
        }
        cp_commit();
        cp_wait2();         // chunk c complete
        __syncthreads();

        const uint32_t sA = sbase + (uint32_t)st_comp * STG_BYTES;

#pragma unroll
        for (int kk = 0; kk < 4; kk++) {
            const uint32_t ko = (uint32_t)kk * 32;   // 16 halves
            uint32_t af[2][4];
            ldm_x4(af[0][0], af[0][1], af[0][2], af[0][3], sA + a_off + ko);
            ldm_x4(af[1][0], af[1][1], af[1][2], af[1][3], sA + a_off + 16 * HSTR * 2 + ko);
            uint32_t bf[8][2];
#pragma unroll
            for (int j = 0; j < 4; j++) {
                ldm_x4(bf[2 * j][0], bf[2 * j][1], bf[2 * j + 1][0], bf[2 * j + 1][1],
                       sA + b_off + (uint32_t)j * 16 * HSTR * 2 + ko);
            }
#pragma unroll
            for (int nt = 0; nt < 8; nt++) {
                mma_f16(acc[0][nt], af[0], bf[nt][0], bf[nt][1]);
                mma_f16(acc[1][nt], af[1], bf[nt][0], bf[nt][1]);
            }
        }
        __syncthreads();

        st_issue = (st_issue == 2) ? 0 : st_issue + 1;
        st_comp  = (st_comp  == 2) ? 0 : st_comp  + 1;
    }
}

// ---------------------------------------------------------------------------
// GEMM1: h = fp16(gelu(x @ W1^T + b1)), nested slices, grouped by expert
// ---------------------------------------------------------------------------
__global__ void __launch_bounds__(256, 2) k_mma1(const float* __restrict__ b1)
{
    const int m = blockIdx.z;
    const int count = g_counts[m];
    const int row0 = blockIdx.y * BM;
    if (row0 >= count) return;
    const int dhid = HDIM >> (NEXP - 1 - m);
    const int col0 = blockIdx.x * BN;
    if (col0 >= dhid) return;
    const int din = DDIM >> (NEXP - 1 - m);

    extern __shared__ __align__(16) __half smem[];
    uint32_t sbase = smem_u32(smem);

    float acc[2][8][4] = {};
    run_mainloop(acc, sbase, m, count, row0, col0, g_xh, DDIM, g_w1, DDIM, din);

    const int tid = threadIdx.x;
    const int lane = tid & 31, wid = tid >> 5;
    const int wm = wid & 3, wn = wid >> 2;
    const int g = lane >> 2, tg = lane & 3;

#pragma unroll
    for (int mt = 0; mt < 2; mt++) {
#pragma unroll
        for (int hr = 0; hr < 2; hr++) {
            int r = row0 + wm * 32 + mt * 16 + g + hr * 8;
            if (r < count) {
                int tok = g_perm[m * T_TOT + r];
                __half* hrow = g_h + (size_t)tok * HDIM + col0;
#pragma unroll
                for (int nt = 0; nt < 8; nt++) {
                    int cc = wn * 64 + nt * 8 + tg * 2;
                    float v0 = gelu_exact(acc[mt][nt][hr * 2 + 0] + b1[col0 + cc]);
                    float v1 = gelu_exact(acc[mt][nt][hr * 2 + 1] + b1[col0 + cc + 1]);
                    *(__half2*)(hrow + cc) = __floats2half2_rn(v0, v1);
                }
            }
        }
    }
}

// ---------------------------------------------------------------------------
// GEMM2: out = h @ W2^T + b2 (fp32 out), K = nested dhid, grouped by expert
// ---------------------------------------------------------------------------
__global__ void __launch_bounds__(256, 2) k_mma2(const float* __restrict__ b2,
                                                 float* __restrict__ out)
{
    const int m = blockIdx.z;
    const int count = g_counts[m];
    const int row0 = blockIdx.y * BM;
    if (row0 >= count) return;
    const int col0 = blockIdx.x * BN;          // N = DDIM, always valid
    const int dhid = HDIM >> (NEXP - 1 - m);

    extern __shared__ __align__(16) __half smem[];
    uint32_t sbase = smem_u32(smem);

    float acc[2][8][4] = {};
    run_mainloop(acc, sbase, m, count, row0, col0, g_h, HDIM, g_w2, HDIM, dhid);

    const int tid = threadIdx.x;
    const int lane = tid & 31, wid = tid >> 5;
    const int wm = wid & 3, wn = wid >> 2;
    const int g = lane >> 2, tg = lane & 3;

#pragma unroll
    for (int mt = 0; mt < 2; mt++) {
#pragma unroll
        for (int hr = 0; hr < 2; hr++) {
            int r = row0 + wm * 32 + mt * 16 + g + hr * 8;
            if (r < count) {
                int tok = g_perm[m * T_TOT + r];
                float* orow = out + (size_t)tok * DDIM + col0;
#pragma unroll
                for (int nt = 0; nt < 8; nt++) {
                    int cc = wn * 64 + nt * 8 + tg * 2;
                    orow[cc]     = acc[mt][nt][hr * 2 + 0] + b2[col0 + cc];
                    orow[cc + 1] = acc[mt][nt][hr * 2 + 1] + b2[col0 + cc + 1];
                }
            }
        }
    }
}

// ---------------------------------------------------------------------------
// Launch
// inputs: 0:x [B,T,D] f32, 1:token_mask [B,T] i32, 2:W1 [H,D] f32,
//         3:b1 [H] f32, 4:W2 [D,H] f32, 5:b2 [D] f32 ; out [B,T,D] f32
// ---------------------------------------------------------------------------
extern "C" void kernel_launch(void* const* d_in, const int* in_sizes, int n_in,
                              void* d_out, int out_size) {
    const float* x    = (const float*)d_in[0];
    const int*   mask = (const int*)  d_in[1];
    const float* W1   = (const float*)d_in[2];
    const float* b1   = (const float*)d_in[3];
    const float* W2   = (const float*)d_in[4];
    const float* b2   = (const float*)d_in[5];
    float* out = (float*)d_out;

    static int attr_done = 0;
    if (!attr_done) {
        cudaFuncSetAttribute(k_mma1, cudaFuncAttributeMaxDynamicSharedMemorySize, SMEM_TOTAL);
        cudaFuncSetAttribute(k_mma2, cudaFuncAttributeMaxDynamicSharedMemorySize, SMEM_TOTAL);
        attr_done = 1;
    }

    void* xh; cudaGetSymbolAddress(&xh, g_xh);
    void* w1; cudaGetSymbolAddress(&w1, g_w1);
    void* w2; cudaGetSymbolAddress(&w2, g_w2);

    const int NX = T_TOT * DDIM / 4, NW1 = HDIM * DDIM / 4, NW2 = DDIM * HDIM / 4;
    k_cvt_h<<<(NX  + 255) / 256, 256>>>((const float4*)x,  (uint2*)xh, NX);
    k_cvt_h<<<(NW1 + 255) / 256, 256>>>((const float4*)W1, (uint2*)w1, NW1);
    k_cvt_h<<<(NW2 + 255) / 256, 256>>>((const float4*)W2, (uint2*)w2, NW2);

    k_init_counts<<<1, 32>>>();
    k_scatter<<<(T_TOT + 255) / 256, 256>>>(mask);

    dim3 g1(HDIM / BN, T_TOT / BM, NEXP);   // most blocks exit early per nesting
    k_mma1<<<g1, 256, SMEM_TOTAL>>>(b1);

    dim3 g2(DDIM / BN, T_TOT / BM, NEXP);
    k_mma2<<<g2, 256, SMEM_TOTAL>>>(b2, out);
}

// round 17
// speedup vs baseline: 7.1858x; 1.0243x over previous
#include <cuda_runtime.h>
#include <cuda_fp16.h>
#include <math.h>
#include <stdint.h>

// Problem constants: B=4, T=4096, D=1024, H=4*D, 4 nested experts
#define T_TOT 16384
#define DDIM  1024
#define HDIM  4096
#define NEXP  4

#define BM 128
#define BN 128
#define BK 64          // K chunk in halves (4 k-steps of m16n8k16)
#define HSTR 72        // smem row stride in halves (64 data + 8 pad -> conflict-free)
#define NSTAGE 3

#define STG_HALVES ((BM + BN) * HSTR)       // 18432 halves / stage
#define STG_BYTES  (STG_HALVES * 2)         // 36864 B
#define SMEM_TOTAL (NSTAGE * STG_BYTES)     // 110592 B (3-stage)

__device__ int    g_counts[NEXP];
__device__ int    g_perm[NEXP * T_TOT];
// Expert-dense packed hidden: expert m region base T_TOT*prefix(m), row stride dhid(m)=512<<m
// prefix = {0, 512, 1536, 3584}; total T_TOT*7680 halves = 240 MB
__device__ __align__(256) __half g_h [(size_t)T_TOT * 7680];
__device__ __align__(256) __half g_xh[(size_t)T_TOT * DDIM];   // 32 MB x (fp16)
__device__ __align__(256) __half g_w1[(size_t)HDIM * DDIM];    // 8 MB
__device__ __align__(256) __half g_w2[(size_t)DDIM * HDIM];    // 8 MB

__constant__ int c_hprefix[NEXP] = {0, 512, 1536, 3584};

// ---------------------------------------------------------------------------
// Helpers
// ---------------------------------------------------------------------------
__device__ __forceinline__ uint32_t smem_u32(const void* p) {
    uint32_t a;
    asm("{ .reg .u64 t; cvta.to.shared.u64 t, %1; cvt.u32.u64 %0, t; }" : "=r"(a) : "l"(p));
    return a;
}
__device__ __forceinline__ float gelu_exact(float v) {
    return 0.5f * v * (1.0f + erff(v * 0.70710678118654752f));
}
__device__ __forceinline__ void mma_f16(float* c, const uint32_t* a, uint32_t b0, uint32_t b1) {
    asm volatile(
        "mma.sync.aligned.m16n8k16.row.col.f32.f16.f16.f32 "
        "{%0,%1,%2,%3}, {%4,%5,%6,%7}, {%8,%9}, {%0,%1,%2,%3};"
        : "+f"(c[0]), "+f"(c[1]), "+f"(c[2]), "+f"(c[3])
        : "r"(a[0]), "r"(a[1]), "r"(a[2]), "r"(a[3]), "r"(b0), "r"(b1));
}
__device__ __forceinline__ void ldm_x4(uint32_t& r0, uint32_t& r1, uint32_t& r2, uint32_t& r3,
                                       uint32_t addr) {
    asm volatile("ldmatrix.sync.aligned.m8n8.x4.shared.b16 {%0,%1,%2,%3}, [%4];"
                 : "=r"(r0), "=r"(r1), "=r"(r2), "=r"(r3) : "r"(addr));
}
__device__ __forceinline__ void cp16(uint32_t dst, const void* src) {
    asm volatile("cp.async.cg.shared.global [%0], [%1], 16;" :: "r"(dst), "l"(src) : "memory");
}
__device__ __forceinline__ void cp_commit() { asm volatile("cp.async.commit_group;" ::: "memory"); }
__device__ __forceinline__ void cp_wait1()  { asm volatile("cp.async.wait_group 1;" ::: "memory"); }
__device__ __forceinline__ void cp_wait0()  { asm volatile("cp.async.wait_group 0;" ::: "memory"); }

// ---------------------------------------------------------------------------
// Fused fp32->fp16 conversion for x, W1, W2 + counts zeroing (block 0)
// ---------------------------------------------------------------------------
#define NX4  (T_TOT * DDIM / 4)
#define NW14 (HDIM * DDIM / 4)
#define NW24 (DDIM * HDIM / 4)

__global__ void k_cvt_all(const float4* __restrict__ x,
                          const float4* __restrict__ W1,
                          const float4* __restrict__ W2) {
    int i = blockIdx.x * blockDim.x + threadIdx.x;
    if (blockIdx.x == 0 && threadIdx.x < NEXP) g_counts[threadIdx.x] = 0;

    const float4* src;
    uint2* dst;
    int j = i;
    if (j < NX4)                  { src = x;  dst = (uint2*)g_xh; }
    else if ((j -= NX4) < NW14)   { src = W1; dst = (uint2*)g_w1; }
    else if ((j -= NW14) < NW24)  { src = W2; dst = (uint2*)g_w2; }
    else return;

    float4 v = src[j];
    __half2 lo = __floats2half2_rn(v.x, v.y);
    __half2 hi = __floats2half2_rn(v.z, v.w);
    uint2 o;
    o.x = *(const uint32_t*)&lo;
    o.y = *(const uint32_t*)&hi;
    dst[j] = o;
}

__global__ void k_scatter(const int* __restrict__ mask) {
    int t = blockIdx.x * blockDim.x + threadIdx.x;
    if (t < T_TOT) {
        int e = mask[t];
        int pos = atomicAdd(&g_counts[e], 1);
        g_perm[e * T_TOT + pos] = t;
    }
}

// ---------------------------------------------------------------------------
// Shared mainloop: 3-stage cp.async fp16 staging, single barrier per chunk,
// ldmatrix.x4 fragments, m16n8k16 HMMA.
// A source pointers are fully precomputed by the caller (gather or dense).
// ---------------------------------------------------------------------------
__device__ __forceinline__ void run_mainloop(
    float acc[2][8][4], uint32_t sbase,
    const __half* gsrcA[4], const __half* gsrcB[4],
    int kdim)
{
    const int tid = threadIdx.x;
    const int lane = tid & 31, wid = tid >> 5;
    const int wm = wid & 3, wn = wid >> 2;

    uint32_t sdst[8];
    const __half* gsrc[8];
#pragma unroll
    for (int i = 0; i < 4; i++) {
        int s = tid + i * 256;
        int r = s >> 3, c = s & 7;
        gsrc[i] = gsrcA[i];
        sdst[i] = sbase + (uint32_t)(r * HSTR + c * 8) * 2u;
        gsrc[i + 4] = gsrcB[i];
        sdst[i + 4] = sbase + (uint32_t)((BM + r) * HSTR + c * 8) * 2u;
    }

    // ldmatrix per-lane base offsets (bytes within a stage)
    const uint32_t a_off = 2u * ((uint32_t)(wm * 32 + (lane & 15)) * HSTR + (uint32_t)(lane >> 4) * 8);
    const uint32_t b_off = 2u * ((uint32_t)(BM + wn * 64 + ((lane >> 4) & 1) * 8 + (lane & 7)) * HSTR
                                 + (uint32_t)((lane >> 3) & 1) * 8);

    const int nch = kdim / BK;

    // prologue: chunks 0,1 -> stages 0,1
#pragma unroll
    for (int i = 0; i < 8; i++) cp16(sdst[i], gsrc[i]);
    cp_commit();
    if (nch > 1) {
#pragma unroll
        for (int i = 0; i < 8; i++) cp16(sdst[i] + STG_BYTES, gsrc[i] + BK);
        cp_commit();
    }

    int st_issue = 2;   // stage for chunk c+2
    int st_comp = 0;    // stage for chunk c
    for (int c = 0; c < nch; c++) {
        if (c == nch - 1) cp_wait0(); else cp_wait1();
        __syncthreads();    // separates prior-iteration reads of st_issue from the issue below

        if (c + 2 < nch) {
            const uint32_t bo = (uint32_t)st_issue * STG_BYTES;
            const int k0 = (c + 2) * BK;
#pragma unroll
            for (int i = 0; i < 8; i++) cp16(sdst[i] + bo, gsrc[i] + k0);
            cp_commit();
        }

        const uint32_t sA = sbase + (uint32_t)st_comp * STG_BYTES;
#pragma unroll
        for (int kk = 0; kk < 4; kk++) {
            const uint32_t ko = (uint32_t)kk * 32;   // 16 halves
            uint32_t af[2][4];
            ldm_x4(af[0][0], af[0][1], af[0][2], af[0][3], sA + a_off + ko);
            ldm_x4(af[1][0], af[1][1], af[1][2], af[1][3], sA + a_off + 16 * HSTR * 2 + ko);
            uint32_t bf[8][2];
#pragma unroll
            for (int j = 0; j < 4; j++) {
                ldm_x4(bf[2 * j][0], bf[2 * j][1], bf[2 * j + 1][0], bf[2 * j + 1][1],
                       sA + b_off + (uint32_t)j * 16 * HSTR * 2 + ko);
            }
#pragma unroll
            for (int nt = 0; nt < 8; nt++) {
                mma_f16(acc[0][nt], af[0], bf[nt][0], bf[nt][1]);
                mma_f16(acc[1][nt], af[1], bf[nt][0], bf[nt][1]);
            }
        }

        st_issue = (st_issue == 2) ? 0 : st_issue + 1;
        st_comp  = (st_comp  == 2) ? 0 : st_comp  + 1;
    }
}

// ---------------------------------------------------------------------------
// GEMM1: h[expert-dense] = fp16(gelu(x @ W1^T + b1)); A gathered via g_perm
// ---------------------------------------------------------------------------
__global__ void __launch_bounds__(256, 2) k_mma1(const float* __restrict__ b1)
{
    const int m = blockIdx.z;
    const int count = g_counts[m];
    const int row0 = blockIdx.y * BM;
    if (row0 >= count) return;
    const int dhid = 512 << m;
    const int col0 = blockIdx.x * BN;
    if (col0 >= dhid) return;
    const int din = 128 << m;

    extern __shared__ __align__(16) __half smem[];
    uint32_t sbase = smem_u32(smem);

    const int tid = threadIdx.x;
    const __half* gsrcA[4];
    const __half* gsrcB[4];
#pragma unroll
    for (int i = 0; i < 4; i++) {
        int s = tid + i * 256;
        int r = s >> 3, c = s & 7;
        int arow = row0 + r;
        int pidx = (arow < count) ? arow : 0;
        int tok = g_perm[m * T_TOT + pidx];
        gsrcA[i] = g_xh + (size_t)tok * DDIM + c * 8;
        gsrcB[i] = g_w1 + (size_t)(col0 + r) * DDIM + c * 8;
    }

    float acc[2][8][4] = {};
    run_mainloop(acc, sbase, gsrcA, gsrcB, din);

    const int lane = tid & 31, wid = tid >> 5;
    const int wm = wid & 3, wn = wid >> 2;
    const int g = lane >> 2, tg = lane & 3;

    __half* hbase = g_h + (size_t)T_TOT * c_hprefix[m];
#pragma unroll
    for (int mt = 0; mt < 2; mt++) {
#pragma unroll
        for (int hr = 0; hr < 2; hr++) {
            int r = row0 + wm * 32 + mt * 16 + g + hr * 8;
            if (r < count) {
                __half* hrow = hbase + (size_t)r * dhid + col0;
#pragma unroll
                for (int nt = 0; nt < 8; nt++) {
                    int cc = wn * 64 + nt * 8 + tg * 2;
                    float v0 = gelu_exact(acc[mt][nt][hr * 2 + 0] + b1[col0 + cc]);
                    float v1 = gelu_exact(acc[mt][nt][hr * 2 + 1] + b1[col0 + cc + 1]);
                    *(__half2*)(hrow + cc) = __floats2half2_rn(v0, v1);
                }
            }
        }
    }
}

// ---------------------------------------------------------------------------
// GEMM2: out[token] = h[expert-dense] @ W2^T + b2; dense A, scatter epilogue
// ---------------------------------------------------------------------------
__global__ void __launch_bounds__(256, 2) k_mma2(const float* __restrict__ b2,
                                                 float* __restrict__ out)
{
    const int m = blockIdx.z;
    const int count = g_counts[m];
    const int row0 = blockIdx.y * BM;
    if (row0 >= count) return;
    const int col0 = blockIdx.x * BN;          // N = DDIM, always valid
    const int dhid = 512 << m;

    extern __shared__ __align__(16) __half smem[];
    uint32_t sbase = smem_u32(smem);

    const int tid = threadIdx.x;
    const __half* hbase = g_h + (size_t)T_TOT * c_hprefix[m];
    const __half* gsrcA[4];
    const __half* gsrcB[4];
#pragma unroll
    for (int i = 0; i < 4; i++) {
        int s = tid + i * 256;
        int r = s >> 3, c = s & 7;
        int arow = row0 + r;
        int pidx = (arow < count) ? arow : 0;
        gsrcA[i] = hbase + (size_t)pidx * dhid + c * 8;
        gsrcB[i] = g_w2 + (size_t)(col0 + r) * HDIM + c * 8;
    }

    float acc[2][8][4] = {};
    run_mainloop(acc, sbase, gsrcA, gsrcB, dhid);

    const int lane = tid & 31, wid = tid >> 5;
    const int wm = wid & 3, wn = wid >> 2;
    const int g = lane >> 2, tg = lane & 3;

#pragma unroll
    for (int mt = 0; mt < 2; mt++) {
#pragma unroll
        for (int hr = 0; hr < 2; hr++) {
            int r = row0 + wm * 32 + mt * 16 + g + hr * 8;
            if (r < count) {
                int tok = g_perm[m * T_TOT + r];
                float* orow = out + (size_t)tok * DDIM + col0;
#pragma unroll
                for (int nt = 0; nt < 8; nt++) {
                    int cc = wn * 64 + nt * 8 + tg * 2;
                    orow[cc]     = acc[mt][nt][hr * 2 + 0] + b2[col0 + cc];
                    orow[cc + 1] = acc[mt][nt][hr * 2 + 1] + b2[col0 + cc + 1];
                }
            }
        }
    }
}

// ---------------------------------------------------------------------------
// Launch
// inputs: 0:x [B,T,D] f32, 1:token_mask [B,T] i32, 2:W1 [H,D] f32,
//         3:b1 [H] f32, 4:W2 [D,H] f32, 5:b2 [D] f32 ; out [B,T,D] f32
// ---------------------------------------------------------------------------
extern "C" void kernel_launch(void* const* d_in, const int* in_sizes, int n_in,
                              void* d_out, int out_size) {
    const float* x    = (const float*)d_in[0];
    const int*   mask = (const int*)  d_in[1];
    const float* W1   = (const float*)d_in[2];
    const float* b1   = (const float*)d_in[3];
    const float* W2   = (const float*)d_in[4];
    const float* b2   = (const float*)d_in[5];
    float* out = (float*)d_out;

    static int attr_done = 0;
    if (!attr_done) {
        cudaFuncSetAttribute(k_mma1, cudaFuncAttributeMaxDynamicSharedMemorySize, SMEM_TOTAL);
        cudaFuncSetAttribute(k_mma2, cudaFuncAttributeMaxDynamicSharedMemorySize, SMEM_TOTAL);
        attr_done = 1;
    }

    const int NTOT4 = NX4 + NW14 + NW24;
    k_cvt_all<<<(NTOT4 + 255) / 256, 256>>>((const float4*)x, (const float4*)W1,
                                            (const float4*)W2);
    k_scatter<<<(T_TOT + 255) / 256, 256>>>(mask);

    dim3 g1(HDIM / BN, T_TOT / BM, NEXP);   // most blocks exit early per nesting
    k_mma1<<<g1, 256, SMEM_TOTAL>>>(b1);

    dim3 g2(DDIM / BN, T_TOT / BM, NEXP);
    k_mma2<<<g2, 256, SMEM_TOTAL>>>(b2, out);
}